// round 1
// baseline (speedup 1.0000x reference)
#include <cuda_runtime.h>

// ---------------- scratch (static device globals; no allocation) ----------------
__device__ float g_sig[64 * 4080];        // signature features, (64, 34*120) row-major
__device__ float g_hp[17 * 64 * 512];     // split-K partials of hidden layer

// ================= Kernel 1: depth-4 path signature =================
// 2176 paths (64 b x 34 vm), T=300 -> 299 segments.
// Each block: 8 consecutive paths x 16 time-chunks = 128 threads.
// Chunk-local signature via fused Chen step, then 4-level tree combine in smem.

__global__ void __launch_bounds__(128) sig_kernel(const float* __restrict__ inp)
{
    __shared__ float xch[64][121];  // odd row stride -> conflict-free exchange

    const int tid = threadIdx.x;
    const int pl = tid & 7;         // path within block (fast -> coalesced)
    const int chunk = tid >> 3;     // 0..15
    const int p = blockIdx.x * 8 + pl;
    const int b = p / 34;
    const int vm = p - b * 34;
    const float* base = inp + b * 30600 + vm;   // inp[b][c][t][vm]: + c*10200 + t*34

    const int s0 = (chunk * 299) >> 4;
    const int s1 = ((chunk + 1) * 299) >> 4;

    float c1[3], c2[9], c3[27], c4[81];
#pragma unroll
    for (int i = 0; i < 3; i++) c1[i] = 0.f;
#pragma unroll
    for (int i = 0; i < 9; i++) c2[i] = 0.f;
#pragma unroll
    for (int i = 0; i < 27; i++) c3[i] = 0.f;
#pragma unroll
    for (int i = 0; i < 81; i++) c4[i] = 0.f;

    float xp[3], xc[3];
#pragma unroll
    for (int c = 0; c < 3; c++) xp[c] = __ldg(base + c * 10200 + s0 * 34);
#pragma unroll
    for (int c = 0; c < 3; c++) xc[c] = __ldg(base + c * 10200 + (s0 + 1) * 34);

    for (int s = s0; s < s1; ++s) {
        int tn = s + 2; if (tn > 299) tn = 299;   // clamped prefetch
        float xn[3];
#pragma unroll
        for (int c = 0; c < 3; c++) xn[c] = __ldg(base + c * 10200 + tn * 34);

        float dx[3], dxh[3], dx3[3];
#pragma unroll
        for (int c = 0; c < 3; c++) {
            dx[c]  = xc[c] - xp[c];
            dxh[c] = 0.5f * dx[c];
            dx3[c] = (1.0f / 3.0f) * dx[c];
        }
        float u2[9];   // dx (x) dx / 2
#pragma unroll
        for (int i = 0; i < 3; i++)
#pragma unroll
            for (int j = 0; j < 3; j++)
                u2[i * 3 + j] = dxh[i] * dx[j];

        float e[3], bq[3], a[3];
#pragma unroll
        for (int i = 0; i < 3; i++) {
            e[i]  = fmaf(0.25f, dx[i], c1[i]);  // c1 + dx/4
            bq[i] = c1[i] + dx3[i];             // c1 + dx/3
            a[i]  = c1[i] + dxh[i];             // c1 + dx/2
        }
        float q[9];   // c2 + e (x) dx/3  -> (q (x) u2) = c2(x)dx^2/2 + c1(x)dx^3/6 + dx^4/24
#pragma unroll
        for (int i = 0; i < 3; i++)
#pragma unroll
            for (int j = 0; j < 3; j++)
                q[i * 3 + j] = fmaf(e[i], dx3[j], c2[i * 3 + j]);

        // level 4 (uses old c1..c3): 2 FMA per element
#pragma unroll
        for (int i = 0; i < 3; i++)
#pragma unroll
            for (int j = 0; j < 3; j++)
#pragma unroll
                for (int k = 0; k < 3; k++)
#pragma unroll
                    for (int l = 0; l < 3; l++) {
                        const int x = i * 27 + j * 9 + k * 3 + l;
                        c4[x] = fmaf(c3[i * 9 + j * 3 + k], dx[l],
                                fmaf(q[i * 3 + j], u2[k * 3 + l], c4[x]));
                    }
        // level 3
#pragma unroll
        for (int i = 0; i < 3; i++)
#pragma unroll
            for (int j = 0; j < 3; j++)
#pragma unroll
                for (int k = 0; k < 3; k++) {
                    const int x = i * 9 + j * 3 + k;
                    c3[x] = fmaf(c2[i * 3 + j], dx[k],
                            fmaf(bq[i], u2[j * 3 + k], c3[x]));
                }
        // level 2
#pragma unroll
        for (int i = 0; i < 3; i++)
#pragma unroll
            for (int j = 0; j < 3; j++)
                c2[i * 3 + j] = fmaf(a[i], dx[j], c2[i * 3 + j]);
        // level 1
#pragma unroll
        for (int i = 0; i < 3; i++) c1[i] += dx[i];

#pragma unroll
        for (int c = 0; c < 3; c++) { xp[c] = xc[c]; xc[c] = xn[c]; }
    }

    // ---- tree combine across chunks (Chen: a = earlier (mine), b = later) ----
#pragma unroll
    for (int d = 0; d < 4; d++) {
        const int step = 1 << d;
        const int m2 = (step << 1) - 1;
        const int slot = pl + 8 * (chunk >> (d + 1));
        __syncthreads();
        if ((chunk & m2) == step) {           // writer: the "later" half
            float* w = xch[slot];
#pragma unroll
            for (int i = 0; i < 3; i++) w[i] = c1[i];
#pragma unroll
            for (int i = 0; i < 9; i++) w[3 + i] = c2[i];
#pragma unroll
            for (int i = 0; i < 27; i++) w[12 + i] = c3[i];
#pragma unroll
            for (int i = 0; i < 81; i++) w[39 + i] = c4[i];
        }
        __syncthreads();
        if ((chunk & m2) == 0) {              // reader/combiner: the "earlier" half
            const float* B = xch[slot];
            float bb1[3], bb2[9], bb3[27];
#pragma unroll
            for (int i = 0; i < 3; i++) bb1[i] = B[i];
#pragma unroll
            for (int i = 0; i < 9; i++) bb2[i] = B[3 + i];
#pragma unroll
            for (int i = 0; i < 27; i++) bb3[i] = B[12 + i];

#pragma unroll
            for (int i = 0; i < 3; i++)
#pragma unroll
                for (int j = 0; j < 3; j++)
#pragma unroll
                    for (int k = 0; k < 3; k++)
#pragma unroll
                        for (int l = 0; l < 3; l++) {
                            const int x = i * 27 + j * 9 + k * 3 + l;
                            c4[x] = fmaf(c3[i * 9 + j * 3 + k], bb1[l],
                                    fmaf(c2[i * 3 + j], bb2[k * 3 + l],
                                    fmaf(c1[i], bb3[j * 9 + k * 3 + l],
                                         c4[x] + B[39 + x])));
                        }
#pragma unroll
            for (int i = 0; i < 3; i++)
#pragma unroll
                for (int j = 0; j < 3; j++)
#pragma unroll
                    for (int k = 0; k < 3; k++) {
                        const int x = i * 9 + j * 3 + k;
                        c3[x] = fmaf(c2[i * 3 + j], bb1[k],
                                fmaf(c1[i], bb2[j * 3 + k], c3[x] + bb3[x]));
                    }
#pragma unroll
            for (int i = 0; i < 3; i++)
#pragma unroll
                for (int j = 0; j < 3; j++)
                    c2[i * 3 + j] = fmaf(c1[i], bb1[j], c2[i * 3 + j] + bb2[i * 3 + j]);
#pragma unroll
            for (int i = 0; i < 3; i++) c1[i] += bb1[i];
        }
    }

    if (chunk == 0) {
        float* out = g_sig + p * 120;
#pragma unroll
        for (int i = 0; i < 3; i++) out[i] = c1[i];
#pragma unroll
        for (int i = 0; i < 9; i++) out[3 + i] = c2[i];
#pragma unroll
        for (int i = 0; i < 27; i++) out[12 + i] = c3[i];
#pragma unroll
        for (int i = 0; i < 81; i++) out[39 + i] = c4[i];
    }
}

// ================= Kernel 2: h-partials = sig @ W1^T (split-K) =================
// C (64 x 512), K = 4080 = 17 slices x 240. Block: 64x64 tile of C over one K-slice.
// Grid (8 col-tiles, 17 k-slices) = 136 blocks. Deterministic partials, no atomics.

__global__ void __launch_bounds__(256) gemm1_kernel(const float* __restrict__ W1)
{
    __shared__ float As[16][68];   // k-major staging (transposed)
    __shared__ float Bs[16][68];

    const int jt = blockIdx.x;          // 0..7
    const int ks = blockIdx.y;          // 0..16
    const int tid = threadIdx.x;
    const int tx = tid & 15;
    const int ty = tid >> 4;
    const int k0 = ks * 240;
    const int j0 = jt * 64;

    const int lrow = tid >> 2;          // 0..63
    const int lk4 = (tid & 3) * 4;      // 0,4,8,12
    const float* Aptr = g_sig + lrow * 4080 + k0 + lk4;
    const float* Bptr = W1 + (j0 + lrow) * 4080 + k0 + lk4;

    float acc[4][4];
#pragma unroll
    for (int r = 0; r < 4; r++)
#pragma unroll
        for (int c = 0; c < 4; c++) acc[r][c] = 0.f;

    for (int kt = 0; kt < 240; kt += 16) {
        const float4 av = *(const float4*)(Aptr + kt);
        const float4 bv = *(const float4*)(Bptr + kt);
        __syncthreads();
        As[lk4 + 0][lrow] = av.x; As[lk4 + 1][lrow] = av.y;
        As[lk4 + 2][lrow] = av.z; As[lk4 + 3][lrow] = av.w;
        Bs[lk4 + 0][lrow] = bv.x; Bs[lk4 + 1][lrow] = bv.y;
        Bs[lk4 + 2][lrow] = bv.z; Bs[lk4 + 3][lrow] = bv.w;
        __syncthreads();
#pragma unroll
        for (int kk = 0; kk < 16; kk++) {
            const float4 a = *(const float4*)&As[kk][ty * 4];
            const float4 bb = *(const float4*)&Bs[kk][tx * 4];
            acc[0][0] = fmaf(a.x, bb.x, acc[0][0]); acc[0][1] = fmaf(a.x, bb.y, acc[0][1]);
            acc[0][2] = fmaf(a.x, bb.z, acc[0][2]); acc[0][3] = fmaf(a.x, bb.w, acc[0][3]);
            acc[1][0] = fmaf(a.y, bb.x, acc[1][0]); acc[1][1] = fmaf(a.y, bb.y, acc[1][1]);
            acc[1][2] = fmaf(a.y, bb.z, acc[1][2]); acc[1][3] = fmaf(a.y, bb.w, acc[1][3]);
            acc[2][0] = fmaf(a.z, bb.x, acc[2][0]); acc[2][1] = fmaf(a.z, bb.y, acc[2][1]);
            acc[2][2] = fmaf(a.z, bb.z, acc[2][2]); acc[2][3] = fmaf(a.z, bb.w, acc[2][3]);
            acc[3][0] = fmaf(a.w, bb.x, acc[3][0]); acc[3][1] = fmaf(a.w, bb.y, acc[3][1]);
            acc[3][2] = fmaf(a.w, bb.z, acc[3][2]); acc[3][3] = fmaf(a.w, bb.w, acc[3][3]);
        }
    }

    float* out = g_hp + ks * 32768;
#pragma unroll
    for (int r = 0; r < 4; r++)
#pragma unroll
        for (int c = 0; c < 4; c++)
            out[(ty * 4 + r) * 512 + j0 + tx * 4 + c] = acc[r][c];
}

// ================= Kernel 3: out = (h + b1) @ W2^T + b2 (folds split-K reduce) ===

__global__ void __launch_bounds__(192) gemm2_kernel(const float* __restrict__ b1,
                                                    const float* __restrict__ W2,
                                                    const float* __restrict__ b2,
                                                    float* __restrict__ out)
{
    __shared__ float hs[512];
    const int i = blockIdx.x;
    const int tid = threadIdx.x;

    for (int k = tid; k < 512; k += 192) {
        float v = b1[k];
#pragma unroll
        for (int s = 0; s < 17; s++) v += g_hp[s * 32768 + i * 512 + k];
        hs[k] = v;
    }
    __syncthreads();

    if (tid < 155) {
        float acc = b2[tid];
        const float* w = W2 + tid * 512;
#pragma unroll 8
        for (int k = 0; k < 512; k += 4) {
            const float4 wv = *(const float4*)(w + k);
            acc = fmaf(hs[k + 0], wv.x, acc);
            acc = fmaf(hs[k + 1], wv.y, acc);
            acc = fmaf(hs[k + 2], wv.z, acc);
            acc = fmaf(hs[k + 3], wv.w, acc);
        }
        out[i * 155 + tid] = acc;
    }
}

// ================================ launch =================================

extern "C" void kernel_launch(void* const* d_in, const int* in_sizes, int n_in,
                              void* d_out, int out_size)
{
    const float* inp = (const float*)d_in[0];
    const float* W1  = (const float*)d_in[1];
    const float* b1  = (const float*)d_in[2];
    const float* W2  = (const float*)d_in[3];
    const float* b2  = (const float*)d_in[4];
    float* out = (float*)d_out;

    sig_kernel<<<272, 128>>>(inp);
    gemm1_kernel<<<dim3(8, 17), 256>>>(W1);
    gemm2_kernel<<<64, 192>>>(b1, W2, b2, out);
}

// round 2
// speedup vs baseline: 1.0588x; 1.0588x over previous
#include <cuda_runtime.h>

// ---------------- scratch (static device globals; no allocation) ----------------
__device__ float g_sig[64 * 4080];          // signature features, (64, 34*120) row-major
__device__ float g_hp[34 * 64 * 512];       // split-K partials of hidden layer

// ================= Kernel 1: depth-4 path signature =================
// 2176 paths (64 b x 34 vm). Block: 4 paths x 32 time-chunks = 128 threads, grid 544.
// Path data staged to smem first (coalesced), factored Chen step (183 ops),
// then 5-level tree combine in smem (overlaid on the staging buffer).

__global__ void __launch_bounds__(128, 3) sig_kernel(const float* __restrict__ inp)
{
    __shared__ float sh[64 * 121];          // 30976 B; [0:3600) doubles as path staging

    const int tid = threadIdx.x;
    const int pl = tid & 3;                  // path within block
    const int chunk = tid >> 2;              // 0..31
    const int pbase = blockIdx.x * 4;

    // ---- stage 4 paths x 300 t x 3 ch into smem: sh[(c*300+t)*4 + pl] ----
    for (int idx = tid; idx < 3600; idx += 128) {
        const int pl2 = idx & 3;
        const int ct = idx >> 2;             // c*300 + t
        const int c = ct / 300;
        const int t = ct - c * 300;
        const int p2 = pbase + pl2;
        const int b = p2 / 34;
        const int vm = p2 - b * 34;
        sh[idx] = __ldg(inp + b * 30600 + c * 10200 + t * 34 + vm);
    }
    __syncthreads();

    const int s0 = (chunk * 299) >> 5;
    const int s1 = ((chunk + 1) * 299) >> 5;

    float c1[3], c2[9], c3[27], c4[81];
#pragma unroll
    for (int i = 0; i < 3; i++) c1[i] = 0.f;
#pragma unroll
    for (int i = 0; i < 9; i++) c2[i] = 0.f;
#pragma unroll
    for (int i = 0; i < 27; i++) c3[i] = 0.f;
#pragma unroll
    for (int i = 0; i < 81; i++) c4[i] = 0.f;

    float xp[3];
#pragma unroll
    for (int c = 0; c < 3; c++) xp[c] = sh[(c * 300 + s0) * 4 + pl];

    for (int s = s0; s < s1; ++s) {
        float dx[3];
#pragma unroll
        for (int c = 0; c < 3; c++) {
            const float xc = sh[(c * 300 + s + 1) * 4 + pl];
            dx[c] = xc - xp[c];
            xp[c] = xc;
        }
        float dxh[3], dx3[3], e[3], bq[3], a[3];
#pragma unroll
        for (int i = 0; i < 3; i++) {
            dxh[i] = 0.5f * dx[i];
            dx3[i] = (1.0f / 3.0f) * dx[i];
            e[i]  = fmaf(0.25f, dx[i], c1[i]);   // c1 + dx/4
            bq[i] = c1[i] + dx3[i];              // c1 + dx/3
            a[i]  = c1[i] + dxh[i];              // c1 + dx/2
        }
        float q[9], sx[9];
#pragma unroll
        for (int i = 0; i < 3; i++)
#pragma unroll
            for (int j = 0; j < 3; j++) {
                q[i * 3 + j]  = fmaf(e[i],  dx3[j], c2[i * 3 + j]);
                sx[i * 3 + j] = fmaf(bq[i], dxh[j], c2[i * 3 + j]);
            }
        // level 4: c4 += (c3[ijk] + q[ij]*dxh[k]) * dx[l]   (108 FMA)
#pragma unroll
        for (int i = 0; i < 3; i++)
#pragma unroll
            for (int j = 0; j < 3; j++)
#pragma unroll
                for (int k = 0; k < 3; k++) {
                    const float r = fmaf(q[i * 3 + j], dxh[k], c3[i * 9 + j * 3 + k]);
                    const int x0 = i * 27 + j * 9 + k * 3;
#pragma unroll
                    for (int l = 0; l < 3; l++)
                        c4[x0 + l] = fmaf(r, dx[l], c4[x0 + l]);
                }
        // level 3: c3 += sx[ij] * dx[k]   (27 FMA)
#pragma unroll
        for (int i = 0; i < 3; i++)
#pragma unroll
            for (int j = 0; j < 3; j++)
#pragma unroll
                for (int k = 0; k < 3; k++) {
                    const int x = i * 9 + j * 3 + k;
                    c3[x] = fmaf(sx[i * 3 + j], dx[k], c3[x]);
                }
        // level 2
#pragma unroll
        for (int i = 0; i < 3; i++)
#pragma unroll
            for (int j = 0; j < 3; j++)
                c2[i * 3 + j] = fmaf(a[i], dx[j], c2[i * 3 + j]);
        // level 1
#pragma unroll
        for (int i = 0; i < 3; i++) c1[i] += dx[i];
    }

    // ---- tree combine across 32 chunks (a = earlier (mine), B = later) ----
#pragma unroll
    for (int d = 0; d < 5; d++) {
        const int step = 1 << d;
        const int m2 = (step << 1) - 1;
        const int slot = pl + 4 * (chunk >> (d + 1));
        __syncthreads();
        if ((chunk & m2) == step) {           // writer: later half
            float* w = sh + slot * 121;
#pragma unroll
            for (int i = 0; i < 3; i++) w[i] = c1[i];
#pragma unroll
            for (int i = 0; i < 9; i++) w[3 + i] = c2[i];
#pragma unroll
            for (int i = 0; i < 27; i++) w[12 + i] = c3[i];
#pragma unroll
            for (int i = 0; i < 81; i++) w[39 + i] = c4[i];
        }
        __syncthreads();
        if ((chunk & m2) == 0) {              // reader/combiner: earlier half
            const float* B = sh + slot * 121;
            float bb1[3], bb2[9], bb3[27];
#pragma unroll
            for (int i = 0; i < 3; i++) bb1[i] = B[i];
#pragma unroll
            for (int i = 0; i < 9; i++) bb2[i] = B[3 + i];
#pragma unroll
            for (int i = 0; i < 27; i++) bb3[i] = B[12 + i];

#pragma unroll
            for (int i = 0; i < 3; i++)
#pragma unroll
                for (int j = 0; j < 3; j++)
#pragma unroll
                    for (int k = 0; k < 3; k++)
#pragma unroll
                        for (int l = 0; l < 3; l++) {
                            const int x = i * 27 + j * 9 + k * 3 + l;
                            c4[x] = fmaf(c3[i * 9 + j * 3 + k], bb1[l],
                                    fmaf(c2[i * 3 + j], bb2[k * 3 + l],
                                    fmaf(c1[i], bb3[j * 9 + k * 3 + l],
                                         c4[x] + B[39 + x])));
                        }
#pragma unroll
            for (int i = 0; i < 3; i++)
#pragma unroll
                for (int j = 0; j < 3; j++)
#pragma unroll
                    for (int k = 0; k < 3; k++) {
                        const int x = i * 9 + j * 3 + k;
                        c3[x] = fmaf(c2[i * 3 + j], bb1[k],
                                fmaf(c1[i], bb2[j * 3 + k], c3[x] + bb3[x]));
                    }
#pragma unroll
            for (int i = 0; i < 3; i++)
#pragma unroll
                for (int j = 0; j < 3; j++)
                    c2[i * 3 + j] = fmaf(c1[i], bb1[j], c2[i * 3 + j] + bb2[i * 3 + j]);
#pragma unroll
            for (int i = 0; i < 3; i++) c1[i] += bb1[i];
        }
    }

    // ---- park results in smem, then coalesced store of 480 floats ----
    __syncthreads();
    if (chunk == 0) {
        float* w = sh + pl * 121;
#pragma unroll
        for (int i = 0; i < 3; i++) w[i] = c1[i];
#pragma unroll
        for (int i = 0; i < 9; i++) w[3 + i] = c2[i];
#pragma unroll
        for (int i = 0; i < 27; i++) w[12 + i] = c3[i];
#pragma unroll
        for (int i = 0; i < 81; i++) w[39 + i] = c4[i];
    }
    __syncthreads();
    for (int idx = tid; idx < 480; idx += 128) {
        const int pp = idx / 120;
        const int r = idx - pp * 120;
        g_sig[pbase * 120 + idx] = sh[pp * 121 + r];
    }
}

// ================= Kernel 2: h-partials = sig @ W1^T (split-K 34) =================
// C (64 x 512). Grid (16 j-tiles of 32, 34 k-slices of 120) = 544 blocks, 128 thr.
// Tile 64x32, microtile 4x4, k-staging of 8 with register prefetch.

__global__ void __launch_bounds__(128) gemm1_kernel(const float* __restrict__ W1)
{
    __shared__ float As[8][68];
    __shared__ float Bs[8][36];

    const int jt = blockIdx.x;          // 0..15
    const int ks = blockIdx.y;          // 0..33
    const int tid = threadIdx.x;
    const int tx = tid & 7;             // 0..7  -> 4 cols each
    const int ty = tid >> 3;            // 0..15 -> 4 rows each
    const int k0 = ks * 120;
    const int j0 = jt * 32;

    const int lrow = tid >> 1;          // 0..63
    const int lk4 = (tid & 1) * 4;      // 0 or 4
    const float* Aptr = g_sig + lrow * 4080 + k0 + lk4;
    const float* Bptr = W1 + (j0 + (lrow & 31)) * 4080 + k0 + lk4;
    const bool bload = (tid < 64);

    float acc[4][4];
#pragma unroll
    for (int r = 0; r < 4; r++)
#pragma unroll
        for (int c = 0; c < 4; c++) acc[r][c] = 0.f;

    float4 av = *(const float4*)(Aptr);
    float4 bv = bload ? *(const float4*)(Bptr) : make_float4(0, 0, 0, 0);

    for (int kt = 0; kt < 120; kt += 8) {
        __syncthreads();
        As[lk4 + 0][lrow] = av.x; As[lk4 + 1][lrow] = av.y;
        As[lk4 + 2][lrow] = av.z; As[lk4 + 3][lrow] = av.w;
        if (bload) {
            Bs[lk4 + 0][lrow] = bv.x; Bs[lk4 + 1][lrow] = bv.y;
            Bs[lk4 + 2][lrow] = bv.z; Bs[lk4 + 3][lrow] = bv.w;
        }
        if (kt < 112) {                       // prefetch next tile
            av = *(const float4*)(Aptr + kt + 8);
            if (bload) bv = *(const float4*)(Bptr + kt + 8);
        }
        __syncthreads();
#pragma unroll
        for (int kk = 0; kk < 8; kk++) {
            const float4 a = *(const float4*)&As[kk][ty * 4];
            const float4 bb = *(const float4*)&Bs[kk][tx * 4];
            acc[0][0] = fmaf(a.x, bb.x, acc[0][0]); acc[0][1] = fmaf(a.x, bb.y, acc[0][1]);
            acc[0][2] = fmaf(a.x, bb.z, acc[0][2]); acc[0][3] = fmaf(a.x, bb.w, acc[0][3]);
            acc[1][0] = fmaf(a.y, bb.x, acc[1][0]); acc[1][1] = fmaf(a.y, bb.y, acc[1][1]);
            acc[1][2] = fmaf(a.y, bb.z, acc[1][2]); acc[1][3] = fmaf(a.y, bb.w, acc[1][3]);
            acc[2][0] = fmaf(a.z, bb.x, acc[2][0]); acc[2][1] = fmaf(a.z, bb.y, acc[2][1]);
            acc[2][2] = fmaf(a.z, bb.z, acc[2][2]); acc[2][3] = fmaf(a.z, bb.w, acc[2][3]);
            acc[3][0] = fmaf(a.w, bb.x, acc[3][0]); acc[3][1] = fmaf(a.w, bb.y, acc[3][1]);
            acc[3][2] = fmaf(a.w, bb.z, acc[3][2]); acc[3][3] = fmaf(a.w, bb.w, acc[3][3]);
        }
    }

    float* outp = g_hp + ks * 32768 + j0;
#pragma unroll
    for (int r = 0; r < 4; r++) {
        float4 v = make_float4(acc[r][0], acc[r][1], acc[r][2], acc[r][3]);
        *(float4*)(outp + (ty * 4 + r) * 512 + tx * 4) = v;
    }
}

// ====== Kernel 3: out = (sum_s hp_s + b1) @ W2^T + b2, grid (64 rows, 5 j-tiles) ======

__global__ void __launch_bounds__(256) gemm2_kernel(const float* __restrict__ b1,
                                                    const float* __restrict__ W2,
                                                    const float* __restrict__ b2,
                                                    float* __restrict__ out)
{
    __shared__ float hs[512];
    const int i = blockIdx.x;
    const int jt = blockIdx.y;
    const int tid = threadIdx.x;

    // phase 1: 34-way reduce + b1 (redundant across jt; g_hp is L2-resident)
    for (int k = tid; k < 512; k += 256) {
        float v0 = b1[k], v1 = 0.f;
        const float* hp = g_hp + i * 512 + k;
#pragma unroll
        for (int s = 0; s < 34; s += 2) {
            v0 += hp[s * 32768];
            v1 += hp[(s + 1) * 32768];
        }
        hs[k] = v0 + v1;
    }
    __syncthreads();

    // phase 2: 8 lanes per output, coalesced W2 float4 reads, shfl reduce
    const int jl = tid >> 3;            // 0..31
    const int ell = tid & 7;            // 0..7
    if (jl < 31) {
        const int j = jt * 31 + jl;     // <= 154
        const float4* w = (const float4*)(W2 + j * 512) + ell;
        float acc0 = 0.f, acc1 = 0.f;
#pragma unroll
        for (int it = 0; it < 16; it += 2) {
            const float4 w0 = w[it * 8];
            const float4 w1 = w[(it + 1) * 8];
            const float* h0 = &hs[(ell + it * 8) * 4];
            const float* h1 = &hs[(ell + (it + 1) * 8) * 4];
            acc0 = fmaf(h0[0], w0.x, acc0); acc0 = fmaf(h0[1], w0.y, acc0);
            acc0 = fmaf(h0[2], w0.z, acc0); acc0 = fmaf(h0[3], w0.w, acc0);
            acc1 = fmaf(h1[0], w1.x, acc1); acc1 = fmaf(h1[1], w1.y, acc1);
            acc1 = fmaf(h1[2], w1.z, acc1); acc1 = fmaf(h1[3], w1.w, acc1);
        }
        float acc = acc0 + acc1;
#pragma unroll
        for (int m = 1; m < 8; m <<= 1)
            acc += __shfl_xor_sync(0xffffffffu, acc, m);
        if (ell == 0) out[i * 155 + j] = acc + b2[j];
    }
}

// ================================ launch =================================

extern "C" void kernel_launch(void* const* d_in, const int* in_sizes, int n_in,
                              void* d_out, int out_size)
{
    const float* inp = (const float*)d_in[0];
    const float* W1  = (const float*)d_in[1];
    const float* b1  = (const float*)d_in[2];
    const float* W2  = (const float*)d_in[3];
    const float* b2  = (const float*)d_in[4];
    float* out = (float*)d_out;

    sig_kernel<<<544, 128>>>(inp);
    gemm1_kernel<<<dim3(16, 34), 128>>>(W1);
    gemm2_kernel<<<dim3(64, 5), 256>>>(b1, W2, b2, out);
}